// round 9
// baseline (speedup 1.0000x reference)
#include <cuda_runtime.h>
#include <math.h>

#define BB 4
#define NN 2048
#define CC 32
#define CONV 332.07156f
#define EPS 1e-6f

// ---- fused geometry: symmetric 512-row panels ----
#define PTHREADS 256
#define PIB 2                       // i-atoms per thread -> panel = 512
#define PANEL 512
#define BLKS_PER_B 148              // splits 59+44+30+15 over panels 0..3
#define PBLOCKS (BB * BLKS_PER_B)   // 592 = 4 CTAs/SM on 148 SMs
#define ES_PER_BLK 14               // ceil(2048/148) self-atoms per block
#define MAXB 48                     // max loop-B j-range (actual <= 35)

// Scratch (no cudaMalloc allowed)
__device__ double g_part[PBLOCKS];  // self + 0.5*pair per block
__device__ unsigned int g_counter = 0;

__device__ __forceinline__ float dot32(const float4* __restrict__ e4,
                                       const float4* __restrict__ f4) {
    float s = 0.f;
#pragma unroll
    for (int c = 0; c < CC / 4; c++) {
        float4 e = e4[c], f = f4[c];
        s = fmaf(e.x, f.x, fmaf(e.y, f.y, fmaf(e.z, f.z, fmaf(e.w, f.w, s))));
    }
    return s;
}

// ONE kernel: per-block staging (w + coords), symmetric pair loops,
// distributed E_self + exact diagonal correction, last-block finalize.
__global__ void __launch_bounds__(PTHREADS, 4)
fused_kernel(const float* __restrict__ X,
             const float* __restrict__ embs,
             const float* __restrict__ qs,
             const float* __restrict__ born,
             const float* __restrict__ die,
             const float* __restrict__ filt,
             float* __restrict__ out)
{
    __shared__ float4 sP[PANEL];        // panel atoms {-x,-y,-z,w}
    __shared__ float4 sE[MAXB];         // loop-B extra atoms
    __shared__ double red[PTHREADS / 32];
    __shared__ bool isLast;

    const int tid = threadIdx.x;
    const int blk = blockIdx.x;
    const int b   = blk / BLKS_PER_B;
    const int r   = blk % BLKS_PER_B;

    // panel + split within panel (splits: 59, 44, 30, 15)
    int p, rl, ns;
    if      (r <  59) { p = 0; rl = r;       ns = 59; }
    else if (r < 103) { p = 1; rl = r -  59; ns = 44; }
    else if (r < 133) { p = 2; rl = r - 103; ns = 30; }
    else              { p = 3; rl = r - 133; ns = 15; }

    const int lo  = PANEL * p;
    const int len = NN - lo;
    const int j0  = lo + (rl * len) / ns;
    const int j1  = lo + ((rl + 1) * len) / ns;
    const int selfEnd = lo + PANEL;
    const int jA1 = (j1 < selfEnd) ? j1 : selfEnd;
    const int jB0 = (j0 > selfEnd) ? j0 : selfEnd;
    const int bcnt = j1 - jB0;              // <= 35, may be <= 0

    const float* Xb = X    + (long)b * NN * 3;
    const float* Eb = embs + (long)b * NN * CC;
    const float4* fi = (const float4*)filt;
    const float4* fj = (const float4*)(filt + CC);
    const float wd = filt[2 * CC];

    // ---- stage this block's 512 panel atoms: w = s_i + s_j, negated coords ----
#pragma unroll
    for (int k = 0; k < PIB; k++) {
        int a = lo + k * PTHREADS + tid;
        const float4* e4 = (const float4*)(Eb + (long)a * CC);
        float w = dot32(e4, fi) + dot32(e4, fj);
        sP[k * PTHREADS + tid] =
            make_float4(-Xb[a * 3], -Xb[a * 3 + 1], -Xb[a * 3 + 2], w);
    }
    // ---- stage loop-B extra atoms ----
    if (tid < bcnt) {
        int a = jB0 + tid;
        const float4* e4 = (const float4*)(Eb + (long)a * CC);
        float w = dot32(e4, fi) + dot32(e4, fj);
        sE[tid] = make_float4(-Xb[a * 3], -Xb[a * 3 + 1], -Xb[a * 3 + 2], w);
    }

    // ---- distributed E_self + exact diagonal correction (coeff-folded) ----
    double part = 0.0;
    {
        int a = ES_PER_BLK * r + tid;
        if (tid < ES_PER_BLK && a < NN) {
            const float4* e4 = (const float4*)(Eb + (long)a * CC);
            float si = dot32(e4, fi);
            float sj = dot32(e4, fj);
            float ad = EPS  + dot32(e4, (const float4*)die);
            float R  = 1.0f + dot32(e4, (const float4*)born);
            float es = -(1.0f - 1.0f / ad) * qs[b * NN + a] / (R + EPS);
            // pair loop credits w*r0_hw + wd for the j==i term; replace with
            // the exact (w + wd*D0)/(D0+eps), using the identical MUFU r0.
            float d2c = 3e-6f;
            asm volatile("" : "+f"(d2c));    // block constant folding
            float r0 = rsqrtf(d2c);
            double D0 = (double)sqrtf(d2c);
            double w  = (double)si + (double)sj;
            double exact = (w + (double)wd * D0) / (D0 + (double)EPS);
            double loopv = w * (double)r0 + (double)wd;
            part = (double)es + 0.5 * (exact - loopv);
        }
    }
    __syncthreads();

    // ---- this thread's PIB i-atoms (un-negate stored coords) ----
    float xi[PIB], yi[PIB], zi[PIB], wi[PIB], acc[PIB];
#pragma unroll
    for (int k = 0; k < PIB; k++) {
        float4 a = sP[k * PTHREADS + tid];
        xi[k] = -a.x; yi[k] = -a.y; zi[k] = -a.z; wi[k] = a.w;
        acc[k] = 0.f;
    }
    float accw = 0.f;

    // ---- loop A: intra-panel (full sub-matrix, w_i weight) ----
#pragma unroll 4
    for (int j = j0; j < jA1; j++) {
        float4 pj = sP[j - lo];              // LDS.128 broadcast
#pragma unroll
        for (int k = 0; k < PIB; k++) {
            float dx = xi[k] + pj.x;
            float dy = yi[k] + pj.y;
            float dz = zi[k] + pj.z;
            float d2 = fmaf(dx, dx, fmaf(dy, dy, fmaf(dz, dz, 3e-6f)));
            acc[k] += rsqrtf(d2);
        }
    }

    // ---- loop B: cross-panel once, (w_i + w_j) weight ----
#pragma unroll 4
    for (int jj = 0; jj < bcnt; jj++) {
        float4 pj = sE[jj];
#pragma unroll
        for (int k = 0; k < PIB; k++) {
            float dx = xi[k] + pj.x;
            float dy = yi[k] + pj.y;
            float dz = zi[k] + pj.z;
            float d2 = fmaf(dx, dx, fmaf(dy, dy, fmaf(dz, dz, 3e-6f)));
            float rr = rsqrtf(d2);
            acc[k] += rr;
            accw = fmaf(pj.w, rr, accw);     // w_j side of symmetric pair
        }
    }

    // ---- combine: block partial = self_part + 0.5 * pair_part ----
    double pairp = (double)accw;
#pragma unroll
    for (int k = 0; k < PIB; k++)
        pairp += (double)wi[k] * (double)acc[k];
    part += 0.5 * pairp;

#pragma unroll
    for (int off = 16; off > 0; off >>= 1)
        part += __shfl_down_sync(0xffffffffu, part, off);
    if ((tid & 31) == 0) red[tid >> 5] = part;
    __syncthreads();
    if (tid == 0) {
        double s = 0.0;
#pragma unroll
        for (int w = 0; w < PTHREADS / 32; w++) s += red[w];
        g_part[blk] = s;
        __threadfence();
        unsigned int t = atomicAdd(&g_counter, 1u);
        isLast = (t == (unsigned)(gridDim.x - 1));
    }
    __syncthreads();
    if (!isLast) return;

    // ---- finalize: warp w (w<BB) handles batch w ----
    const int w = tid >> 5, lane = tid & 31;
    if (w < BB) {
        double pp = 0.0;
#pragma unroll
        for (int t = 0; t < 5; t++) {
            int idx = lane + t * 32;
            if (idx < BLKS_PER_B) pp += __ldcg(&g_part[w * BLKS_PER_B + idx]);
        }
#pragma unroll
        for (int off = 16; off > 0; off >>= 1)
            pp += __shfl_down_sync(0xffffffffu, pp, off);
        if (lane == 0) {
            pp += 0.5 * (double)wd * (double)NN * (double)NN;
            float v = (float)((double)CONV * pp * 0.01);
            if (isnan(v)) v = 1e-6f;
            out[w] = v;
        }
    }
    if (tid == 0) g_counter = 0;   // reset for next graph replay
}

extern "C" void kernel_launch(void* const* d_in, const int* in_sizes, int n_in,
                              void* d_out, int out_size) {
    const float* X    = (const float*)d_in[0];  // (B,N,3)
    const float* embs = (const float*)d_in[1];  // (B,N,C)
    const float* qs   = (const float*)d_in[2];  // (B,N)
    // d_in[3] = paired_mask (unused by reference)
    const float* born = (const float*)d_in[4];  // (C,)
    const float* die  = (const float*)d_in[5];  // (C,)
    const float* filt = (const float*)d_in[6];  // (2C+1, 1)
    float* out = (float*)d_out;

    fused_kernel<<<PBLOCKS, PTHREADS>>>(X, embs, qs, born, die, filt, out);
}

// round 10
// speedup vs baseline: 1.0904x; 1.0904x over previous
#include <cuda_runtime.h>
#include <math.h>

#define BB 4
#define NN 2048
#define CC 32
#define CONV 332.07156f
#define EPS 1e-6f

// ---- precompute geometry ----
#define PRE_THREADS 256
#define PRE_BLOCKS (BB * NN / PRE_THREADS)   // 32 (8 per batch)

// ---- pair geometry (symmetric 1024-row panels) ----
#define PTHREADS 256
#define PIB 4                       // i-atoms per thread -> panel = 1024
#define PANEL 1024
#define BLKS_PER_B 148              // splits 99+49 over panels 0..1
#define PBLOCKS (BB * BLKS_PER_B)   // 592 = 4 CTAs/SM on 148 SMs

// Scratch (no cudaMalloc allowed)
__device__ float4 g_S[BB * NN];            // {-x, -y, -z, w=s_i+s_j}
__device__ double g_part_pair[PBLOCKS];
__device__ double g_part_self[PRE_BLOCKS]; // self + 0.5*diag-correction
__device__ unsigned int g_counter = 0;

// ============ kernel 1: per-atom precompute + self/diag partials ============
__global__ void __launch_bounds__(PRE_THREADS)
precompute_kernel(const float* __restrict__ X,
                  const float* __restrict__ embs,
                  const float* __restrict__ qs,
                  const float* __restrict__ born,
                  const float* __restrict__ die,
                  const float* __restrict__ filt)
{
    __shared__ double red[PRE_THREADS / 32];
    const int tid = threadIdx.x;
    const int idx = blockIdx.x * PRE_THREADS + tid;
    const float wd = filt[2 * CC];

    const float4* e4 = (const float4*)(embs + (long)idx * CC);
    const float4* fi = (const float4*)(filt);
    const float4* fj = (const float4*)(filt + CC);
    const float4* d4 = (const float4*)(die);
    const float4* b4 = (const float4*)(born);

    float si = 0.f, sj = 0.f, ad = EPS, R = 1.0f;
#pragma unroll
    for (int c = 0; c < CC / 4; c++) {
        float4 e = e4[c];
        float4 a = fi[c], bq = fj[c], d = d4[c], bo = b4[c];
        si = fmaf(e.x, a.x,  fmaf(e.y, a.y,  fmaf(e.z, a.z,  fmaf(e.w, a.w,  si))));
        sj = fmaf(e.x, bq.x, fmaf(e.y, bq.y, fmaf(e.z, bq.z, fmaf(e.w, bq.w, sj))));
        ad = fmaf(e.x, d.x,  fmaf(e.y, d.y,  fmaf(e.z, d.z,  fmaf(e.w, d.w,  ad))));
        R  = fmaf(e.x, bo.x, fmaf(e.y, bo.y, fmaf(e.z, bo.z, fmaf(e.w, bo.w, R))));
    }
    float es = -(1.0f - 1.0f / ad) * qs[idx] / (R + EPS);

    g_S[idx] = make_float4(-X[idx * 3 + 0], -X[idx * 3 + 1], -X[idx * 3 + 2],
                           si + sj);

    // exact diagonal correction: the pair loop credits (si+sj)*r0_hw + wd
    // for the j==i pair; the true value is (si+sj+wd*D0)/(D0+eps).
    double part;
    {
        float d2c = 3e-6f;
        asm volatile("" : "+f"(d2c));        // block constant folding
        float r0_hw = rsqrtf(d2c);           // identical MUFU value as pair loop
        double D0 = (double)sqrtf(d2c);
        double w  = (double)si + (double)sj;
        double exact = (w + (double)wd * D0) / (D0 + (double)EPS);
        double loopv = w * (double)r0_hw + (double)wd;
        double corr = exact - loopv;          // pair-sum channel (coeff 0.5)
        part = (double)es + 0.5 * corr;
    }
#pragma unroll
    for (int off = 16; off > 0; off >>= 1)
        part += __shfl_down_sync(0xffffffffu, part, off);
    if ((tid & 31) == 0) red[tid >> 5] = part;
    __syncthreads();
    if (tid == 0) {
        double s = 0.0;
#pragma unroll
        for (int w = 0; w < PRE_THREADS / 32; w++) s += red[w];
        g_part_self[blockIdx.x] = s;
    }
}

// ============ kernel 2: symmetric pairwise + finalize ============
// Full matrix T = sum_ij w_i r_ij decomposed per 1024-row panel p:
//   intra-panel [lo, lo+1024):        sum w_i r_ij (full sub-matrix)
//   cross-panel [lo+1024, 2048) once: sum (w_i + w_j) r_ij
// E_pair(batch) = T + wd*N^2 (+exact diag corr from k1)
__global__ void __launch_bounds__(PTHREADS, 4)
pair_kernel(const float* __restrict__ filt, float* __restrict__ out)
{
    __shared__ double red[PTHREADS / 32];
    __shared__ bool isLast;

    const int tid = threadIdx.x;
    const int blk = blockIdx.x;
    const int b   = blk / BLKS_PER_B;
    const int r   = blk % BLKS_PER_B;

    // panel + split within panel (splits: 99, 49)
    int p, rl, ns;
    if (r < 99) { p = 0; rl = r;      ns = 99; }
    else        { p = 1; rl = r - 99; ns = 49; }

    const int lo  = PANEL * p;
    const int len = NN - lo;
    const int j0  = lo + (rl * len) / ns;
    const int j1  = lo + ((rl + 1) * len) / ns;
    const int selfEnd = lo + PANEL;
    const int jA1 = (j1 < selfEnd) ? j1 : selfEnd;
    const int jB0 = (j0 > selfEnd) ? j0 : selfEnd;

    const float4* __restrict__ S = g_S + b * NN;

    // this thread's PIB i-atoms within the panel
    float xi[PIB], yi[PIB], zi[PIB], wi[PIB], acc[PIB];
#pragma unroll
    for (int k = 0; k < PIB; k++) {
        float4 a = __ldg(&S[lo + k * PTHREADS + tid]);
        xi[k] = -a.x; yi[k] = -a.y; zi[k] = -a.z; wi[k] = a.w;
        acc[k] = 0.f;
    }
    float accw = 0.f;

    // ---- loop A: intra-panel region (full matrix, w_i weight) ----
#pragma unroll 2
    for (int j = j0; j < jA1; j++) {
        float4 pj = __ldg(&S[j]);          // negated coords, warp-uniform
#pragma unroll
        for (int k = 0; k < PIB; k++) {
            float dx = xi[k] + pj.x;
            float dy = yi[k] + pj.y;
            float dz = zi[k] + pj.z;
            float d2 = fmaf(dx, dx, fmaf(dy, dy, fmaf(dz, dz, 3e-6f)));
            acc[k] += rsqrtf(d2);
        }
    }

    // ---- loop B: cross-panel region (counted once, (w_i + w_j) weight) ----
#pragma unroll 2
    for (int j = jB0; j < j1; j++) {
        float4 pj = __ldg(&S[j]);
#pragma unroll
        for (int k = 0; k < PIB; k++) {
            float dx = xi[k] + pj.x;
            float dy = yi[k] + pj.y;
            float dz = zi[k] + pj.z;
            float d2 = fmaf(dx, dx, fmaf(dy, dy, fmaf(dz, dz, 3e-6f)));
            float rr = rsqrtf(d2);
            acc[k] += rr;
            accw = fmaf(pj.w, rr, accw);   // w_j side of symmetric pair
        }
    }

    // combine in double
    double part = (double)accw;
#pragma unroll
    for (int k = 0; k < PIB; k++)
        part += (double)wi[k] * (double)acc[k];
#pragma unroll
    for (int off = 16; off > 0; off >>= 1)
        part += __shfl_down_sync(0xffffffffu, part, off);
    if ((tid & 31) == 0) red[tid >> 5] = part;
    __syncthreads();
    if (tid == 0) {
        double s = 0.0;
#pragma unroll
        for (int w = 0; w < PTHREADS / 32; w++) s += red[w];
        g_part_pair[blk] = s;
        __threadfence();
        unsigned int t = atomicAdd(&g_counter, 1u);
        isLast = (t == (unsigned)(gridDim.x - 1));
    }
    __syncthreads();
    if (!isLast) return;

    // ---- finalize: warp w (w<BB) handles batch w ----
    const int w = tid >> 5, lane = tid & 31;
    const float wd = filt[2 * CC];

    if (w < BB) {
        double pp = 0.0;
#pragma unroll
        for (int t = 0; t < 5; t++) {
            int idx = lane + t * 32;
            if (idx < BLKS_PER_B) pp += __ldcg(&g_part_pair[w * BLKS_PER_B + idx]);
        }
        double ss = (lane < PRE_BLOCKS / BB)
                  ? __ldcg(&g_part_self[w * (PRE_BLOCKS / BB) + lane]) : 0.0;
#pragma unroll
        for (int off = 16; off > 0; off >>= 1) {
            pp += __shfl_down_sync(0xffffffffu, pp, off);
            ss += __shfl_down_sync(0xffffffffu, ss, off);
        }
        if (lane == 0) {
            double pair = pp + (double)wd * (double)NN * (double)NN;
            float v = (float)((double)CONV * (ss + 0.5 * pair) * 0.01);
            if (isnan(v)) v = 1e-6f;
            out[w] = v;
        }
    }
    if (tid == 0) g_counter = 0;   // reset for next graph replay
}

extern "C" void kernel_launch(void* const* d_in, const int* in_sizes, int n_in,
                              void* d_out, int out_size) {
    const float* X    = (const float*)d_in[0];  // (B,N,3)
    const float* embs = (const float*)d_in[1];  // (B,N,C)
    const float* qs   = (const float*)d_in[2];  // (B,N)
    // d_in[3] = paired_mask (unused by reference)
    const float* born = (const float*)d_in[4];  // (C,)
    const float* die  = (const float*)d_in[5];  // (C,)
    const float* filt = (const float*)d_in[6];  // (2C+1, 1)
    float* out = (float*)d_out;

    precompute_kernel<<<PRE_BLOCKS, PRE_THREADS>>>(X, embs, qs, born, die, filt);
    pair_kernel<<<PBLOCKS, PTHREADS>>>(filt, out);
}

// round 11
// speedup vs baseline: 1.1825x; 1.0845x over previous
#include <cuda_runtime.h>
#include <math.h>

#define BB 4
#define NN 2048
#define CC 32
#define CONV 332.07156f
#define EPS 1e-6f

// ---- geometry: symmetric 512-row panels, one persistent wave ----
#define PTHREADS 256
#define PIB 2                       // i-atoms per thread -> panel = 512
#define PANEL 512
#define BLKS_PER_B 148              // splits 59+44+30+15 over panels 0..3
#define PBLOCKS (BB * BLKS_PER_B)   // 592 = exactly 4 CTAs/SM on 148 SMs
#define ATOMS_PER_BLK 14            // ceil(8192/592) phase-1 atoms per block

// Scratch (no cudaMalloc allowed)
__device__ float4 g_S[BB * NN];     // {-x, -y, -z, w=s_i+s_j}
__device__ double g_part[PBLOCKS];  // (self + diag corr) + 0.5*pair per block
__device__ unsigned int g_arrive = 0;   // grid barrier
__device__ unsigned int g_counter = 0;  // finalize election

__device__ __forceinline__ float dot32(const float4* __restrict__ e4,
                                       const float4* __restrict__ f4) {
    float s = 0.f;
#pragma unroll
    for (int c = 0; c < CC / 4; c++) {
        float4 e = e4[c], f = f4[c];
        s = fmaf(e.x, f.x, fmaf(e.y, f.y, fmaf(e.z, f.z, fmaf(e.w, f.w, s))));
    }
    return s;
}

__global__ void __launch_bounds__(PTHREADS, 4)
fused_kernel(const float* __restrict__ X,
             const float* __restrict__ embs,
             const float* __restrict__ qs,
             const float* __restrict__ born,
             const float* __restrict__ die,
             const float* __restrict__ filt,
             float* __restrict__ out)
{
    __shared__ double red[PTHREADS / 32];
    __shared__ bool isLast;

    const int tid = threadIdx.x;
    const int blk = blockIdx.x;
    const int b   = blk / BLKS_PER_B;
    const int r   = blk % BLKS_PER_B;
    const float wd = filt[2 * CC];

    // ================= phase 1: this block's 1/592 share of g_S =================
    // atom index space: 0 .. B*N-1; block handles [blk*14, blk*14+14)
    double part = 0.0;       // self + 0.5*diag-correction channel
    {
        int a = blk * ATOMS_PER_BLK + tid;
        if (tid < ATOMS_PER_BLK && a < BB * NN) {
            const float4* e4 = (const float4*)(embs + (long)a * CC);
            float si = dot32(e4, (const float4*)filt);
            float sj = dot32(e4, (const float4*)(filt + CC));
            float ad = EPS  + dot32(e4, (const float4*)die);
            float R  = 1.0f + dot32(e4, (const float4*)born);
            float es = -(1.0f - 1.0f / ad) * qs[a] / (R + EPS);

            g_S[a] = make_float4(-X[a * 3], -X[a * 3 + 1], -X[a * 3 + 2], si + sj);

            // exact diagonal correction: pair loop credits w*r0_hw + wd for
            // j==i; true value is (w + wd*D0)/(D0+eps). r0_hw = same MUFU.
            float d2c = 3e-6f;
            asm volatile("" : "+f"(d2c));    // block constant folding
            float r0 = rsqrtf(d2c);
            double D0 = (double)sqrtf(d2c);
            double w  = (double)si + (double)sj;
            double exact = (w + (double)wd * D0) / (D0 + (double)EPS);
            double loopv = w * (double)r0 + (double)wd;
            part = (double)es + 0.5 * (exact - loopv);
        }
    }

    // ================= grid barrier (all 592 CTAs resident: one wave) ===========
    __threadfence();
    __syncthreads();
    if (tid == 0) {
        atomicAdd(&g_arrive, 1u);
        while (*((volatile unsigned int*)&g_arrive) < (unsigned)PBLOCKS)
            __nanosleep(64);
    }
    __syncthreads();
    __threadfence();

    // ================= phase 2: symmetric pair loops (R8 body) ==================
    // panel + split within panel (splits: 59, 44, 30, 15)
    int p, rl, ns;
    if      (r <  59) { p = 0; rl = r;       ns = 59; }
    else if (r < 103) { p = 1; rl = r -  59; ns = 44; }
    else if (r < 133) { p = 2; rl = r - 103; ns = 30; }
    else              { p = 3; rl = r - 133; ns = 15; }

    const int lo  = PANEL * p;
    const int len = NN - lo;
    const int j0  = lo + (rl * len) / ns;
    const int j1  = lo + ((rl + 1) * len) / ns;
    const int selfEnd = lo + PANEL;
    const int jA1 = (j1 < selfEnd) ? j1 : selfEnd;
    const int jB0 = (j0 > selfEnd) ? j0 : selfEnd;

    const float4* __restrict__ S = g_S + b * NN;

    float xi[PIB], yi[PIB], zi[PIB], wi[PIB], acc[PIB];
#pragma unroll
    for (int k = 0; k < PIB; k++) {
        float4 a = __ldg(&S[lo + k * PTHREADS + tid]);
        xi[k] = -a.x; yi[k] = -a.y; zi[k] = -a.z; wi[k] = a.w;
        acc[k] = 0.f;
    }
    float accw = 0.f;

    // loop A: intra-panel (full sub-matrix, w_i weight)
#pragma unroll 4
    for (int j = j0; j < jA1; j++) {
        float4 pj = __ldg(&S[j]);          // negated coords, warp-uniform
#pragma unroll
        for (int k = 0; k < PIB; k++) {
            float dx = xi[k] + pj.x;
            float dy = yi[k] + pj.y;
            float dz = zi[k] + pj.z;
            float d2 = fmaf(dx, dx, fmaf(dy, dy, fmaf(dz, dz, 3e-6f)));
            acc[k] += rsqrtf(d2);
        }
    }

    // loop B: cross-panel once, (w_i + w_j) weight
#pragma unroll 4
    for (int j = jB0; j < j1; j++) {
        float4 pj = __ldg(&S[j]);
#pragma unroll
        for (int k = 0; k < PIB; k++) {
            float dx = xi[k] + pj.x;
            float dy = yi[k] + pj.y;
            float dz = zi[k] + pj.z;
            float d2 = fmaf(dx, dx, fmaf(dy, dy, fmaf(dz, dz, 3e-6f)));
            float rr = rsqrtf(d2);
            acc[k] += rr;
            accw = fmaf(pj.w, rr, accw);   // w_j side of symmetric pair
        }
    }

    // block partial = (self + diag) + 0.5 * pair
    double pairp = (double)accw;
#pragma unroll
    for (int k = 0; k < PIB; k++)
        pairp += (double)wi[k] * (double)acc[k];
    part += 0.5 * pairp;

#pragma unroll
    for (int off = 16; off > 0; off >>= 1)
        part += __shfl_down_sync(0xffffffffu, part, off);
    if ((tid & 31) == 0) red[tid >> 5] = part;
    __syncthreads();
    if (tid == 0) {
        double s = 0.0;
#pragma unroll
        for (int w = 0; w < PTHREADS / 32; w++) s += red[w];
        g_part[blk] = s;
        __threadfence();
        unsigned int t = atomicAdd(&g_counter, 1u);
        isLast = (t == (unsigned)(gridDim.x - 1));
    }
    __syncthreads();
    if (!isLast) return;

    // ================= finalize: warp w (w<BB) handles batch w ==================
    const int w = tid >> 5, lane = tid & 31;
    if (w < BB) {
        double pp = 0.0;
#pragma unroll
        for (int t = 0; t < 5; t++) {
            int idx = lane + t * 32;
            if (idx < BLKS_PER_B) pp += __ldcg(&g_part[w * BLKS_PER_B + idx]);
        }
#pragma unroll
        for (int off = 16; off > 0; off >>= 1)
            pp += __shfl_down_sync(0xffffffffu, pp, off);
        if (lane == 0) {
            pp += 0.5 * (double)wd * (double)NN * (double)NN;
            float v = (float)((double)CONV * pp * 0.01);
            if (isnan(v)) v = 1e-6f;
            out[w] = v;
        }
    }
    // safe reset: finalize runs only after every block passed both counters
    if (tid == 0) { g_counter = 0; g_arrive = 0; }
}

extern "C" void kernel_launch(void* const* d_in, const int* in_sizes, int n_in,
                              void* d_out, int out_size) {
    const float* X    = (const float*)d_in[0];  // (B,N,3)
    const float* embs = (const float*)d_in[1];  // (B,N,C)
    const float* qs   = (const float*)d_in[2];  // (B,N)
    // d_in[3] = paired_mask (unused by reference)
    const float* born = (const float*)d_in[4];  // (C,)
    const float* die  = (const float*)d_in[5];  // (C,)
    const float* filt = (const float*)d_in[6];  // (2C+1, 1)
    float* out = (float*)d_out;

    fused_kernel<<<PBLOCKS, PTHREADS>>>(X, embs, qs, born, die, filt, out);
}

// round 12
// speedup vs baseline: 1.1951x; 1.0107x over previous
#include <cuda_runtime.h>
#include <math.h>

#define BB 4
#define NN 2048
#define CC 32
#define CONV 332.07156f
#define EPS 1e-6f

// ---- precompute geometry ----
#define PRE_THREADS 256
#define PRE_BLOCKS (BB * NN / PRE_THREADS)   // 32 (8 per batch)

// ---- pair geometry (symmetric 256-row panels, fine-grained) ----
#define PTHREADS 128
#define PIB 2                       // i-atoms per thread -> panel = 256
#define PANEL 256
#define BLKS_PER_B 370              // splits 82+72+62+51+41+31+21+10 (8 panels)
#define PBLOCKS (BB * BLKS_PER_B)   // 1480 = 10 CTAs/SM on 148 SMs

// Scratch (no cudaMalloc allowed)
__device__ float4 g_S[BB * NN];            // {-x, -y, -z, w=s_i+s_j}
__device__ double g_part_pair[PBLOCKS];
__device__ double g_part_self[PRE_BLOCKS]; // self + 0.5*diag-correction
__device__ unsigned int g_counter = 0;

// ============ kernel 1: per-atom precompute + self/diag partials ============
__global__ void __launch_bounds__(PRE_THREADS)
precompute_kernel(const float* __restrict__ X,
                  const float* __restrict__ embs,
                  const float* __restrict__ qs,
                  const float* __restrict__ born,
                  const float* __restrict__ die,
                  const float* __restrict__ filt)
{
    __shared__ double red[PRE_THREADS / 32];
    const int tid = threadIdx.x;
    const int idx = blockIdx.x * PRE_THREADS + tid;
    const float wd = filt[2 * CC];

    const float4* e4 = (const float4*)(embs + (long)idx * CC);
    const float4* fi = (const float4*)(filt);
    const float4* fj = (const float4*)(filt + CC);
    const float4* d4 = (const float4*)(die);
    const float4* b4 = (const float4*)(born);

    float si = 0.f, sj = 0.f, ad = EPS, R = 1.0f;
#pragma unroll
    for (int c = 0; c < CC / 4; c++) {
        float4 e = e4[c];
        float4 a = fi[c], bq = fj[c], d = d4[c], bo = b4[c];
        si = fmaf(e.x, a.x,  fmaf(e.y, a.y,  fmaf(e.z, a.z,  fmaf(e.w, a.w,  si))));
        sj = fmaf(e.x, bq.x, fmaf(e.y, bq.y, fmaf(e.z, bq.z, fmaf(e.w, bq.w, sj))));
        ad = fmaf(e.x, d.x,  fmaf(e.y, d.y,  fmaf(e.z, d.z,  fmaf(e.w, d.w,  ad))));
        R  = fmaf(e.x, bo.x, fmaf(e.y, bo.y, fmaf(e.z, bo.z, fmaf(e.w, bo.w, R))));
    }
    float es = -(1.0f - 1.0f / ad) * qs[idx] / (R + EPS);

    g_S[idx] = make_float4(-X[idx * 3 + 0], -X[idx * 3 + 1], -X[idx * 3 + 2],
                           si + sj);

    // exact diagonal correction: the pair loop credits (si+sj)*r0_hw + wd
    // for the j==i pair; the true value is (si+sj+wd*D0)/(D0+eps).
    double part;
    {
        float d2c = 3e-6f;
        asm volatile("" : "+f"(d2c));        // block constant folding
        float r0_hw = rsqrtf(d2c);           // identical MUFU value as pair loop
        double D0 = (double)sqrtf(d2c);
        double w  = (double)si + (double)sj;
        double exact = (w + (double)wd * D0) / (D0 + (double)EPS);
        double loopv = w * (double)r0_hw + (double)wd;
        double corr = exact - loopv;          // pair-sum channel (coeff 0.5)
        part = (double)es + 0.5 * corr;
    }
#pragma unroll
    for (int off = 16; off > 0; off >>= 1)
        part += __shfl_down_sync(0xffffffffu, part, off);
    if ((tid & 31) == 0) red[tid >> 5] = part;
    __syncthreads();
    if (tid == 0) {
        double s = 0.0;
#pragma unroll
        for (int w = 0; w < PRE_THREADS / 32; w++) s += red[w];
        g_part_self[blockIdx.x] = s;
    }
}

// ============ kernel 2: symmetric pairwise + finalize ============
// Full matrix T = sum_ij w_i r_ij decomposed per 256-row panel p:
//   intra-panel [lo, lo+256):        sum w_i r_ij (full sub-matrix)
//   cross-panel [lo+256, 2048) once: sum (w_i + w_j) r_ij
// E_pair(batch) = T + wd*N^2 (+exact diag corr from k1)
__global__ void __launch_bounds__(PTHREADS, 10)
pair_kernel(const float* __restrict__ filt, float* __restrict__ out)
{
    __shared__ double red[PTHREADS / 32];
    __shared__ bool isLast;

    const int tid = threadIdx.x;
    const int blk = blockIdx.x;
    const int b   = blk / BLKS_PER_B;
    const int r   = blk % BLKS_PER_B;

    // panel + split within panel; splits: 82,72,62,51,41,31,21,10 (sum 370)
    int p, rl, ns;
    if      (r <  82) { p = 0; rl = r;       ns = 82; }
    else if (r < 154) { p = 1; rl = r -  82; ns = 72; }
    else if (r < 216) { p = 2; rl = r - 154; ns = 62; }
    else if (r < 267) { p = 3; rl = r - 216; ns = 51; }
    else if (r < 308) { p = 4; rl = r - 267; ns = 41; }
    else if (r < 339) { p = 5; rl = r - 308; ns = 31; }
    else if (r < 360) { p = 6; rl = r - 339; ns = 21; }
    else              { p = 7; rl = r - 360; ns = 10; }

    const int lo  = PANEL * p;
    const int len = NN - lo;
    const int j0  = lo + (rl * len) / ns;
    const int j1  = lo + ((rl + 1) * len) / ns;
    const int selfEnd = lo + PANEL;
    const int jA1 = (j1 < selfEnd) ? j1 : selfEnd;
    const int jB0 = (j0 > selfEnd) ? j0 : selfEnd;

    const float4* __restrict__ S = g_S + b * NN;

    // this thread's PIB i-atoms within the panel
    float xi[PIB], yi[PIB], zi[PIB], wi[PIB], acc[PIB];
#pragma unroll
    for (int k = 0; k < PIB; k++) {
        float4 a = __ldg(&S[lo + k * PTHREADS + tid]);
        xi[k] = -a.x; yi[k] = -a.y; zi[k] = -a.z; wi[k] = a.w;
        acc[k] = 0.f;
    }
    float accw = 0.f;

    // ---- loop A: intra-panel region (full matrix, w_i weight) ----
#pragma unroll 4
    for (int j = j0; j < jA1; j++) {
        float4 pj = __ldg(&S[j]);          // negated coords, warp-uniform
#pragma unroll
        for (int k = 0; k < PIB; k++) {
            float dx = xi[k] + pj.x;
            float dy = yi[k] + pj.y;
            float dz = zi[k] + pj.z;
            float d2 = fmaf(dx, dx, fmaf(dy, dy, fmaf(dz, dz, 3e-6f)));
            acc[k] += rsqrtf(d2);
        }
    }

    // ---- loop B: cross-panel region (counted once, (w_i + w_j) weight) ----
#pragma unroll 4
    for (int j = jB0; j < j1; j++) {
        float4 pj = __ldg(&S[j]);
#pragma unroll
        for (int k = 0; k < PIB; k++) {
            float dx = xi[k] + pj.x;
            float dy = yi[k] + pj.y;
            float dz = zi[k] + pj.z;
            float d2 = fmaf(dx, dx, fmaf(dy, dy, fmaf(dz, dz, 3e-6f)));
            float rr = rsqrtf(d2);
            acc[k] += rr;
            accw = fmaf(pj.w, rr, accw);   // w_j side of symmetric pair
        }
    }

    // combine in double
    double part = (double)accw;
#pragma unroll
    for (int k = 0; k < PIB; k++)
        part += (double)wi[k] * (double)acc[k];
#pragma unroll
    for (int off = 16; off > 0; off >>= 1)
        part += __shfl_down_sync(0xffffffffu, part, off);
    if ((tid & 31) == 0) red[tid >> 5] = part;
    __syncthreads();
    if (tid == 0) {
        double s = 0.0;
#pragma unroll
        for (int w = 0; w < PTHREADS / 32; w++) s += red[w];
        g_part_pair[blk] = s;
        __threadfence();
        unsigned int t = atomicAdd(&g_counter, 1u);
        isLast = (t == (unsigned)(gridDim.x - 1));
    }
    __syncthreads();
    if (!isLast) return;

    // ---- finalize: warp w (w<BB) handles batch w ----
    const int w = tid >> 5, lane = tid & 31;
    const float wd = filt[2 * CC];

    if (w < BB) {
        double pp = 0.0;
#pragma unroll
        for (int t = 0; t < 12; t++) {
            int idx = lane + t * 32;
            if (idx < BLKS_PER_B) pp += __ldcg(&g_part_pair[w * BLKS_PER_B + idx]);
        }
        double ss = (lane < PRE_BLOCKS / BB)
                  ? __ldcg(&g_part_self[w * (PRE_BLOCKS / BB) + lane]) : 0.0;
#pragma unroll
        for (int off = 16; off > 0; off >>= 1) {
            pp += __shfl_down_sync(0xffffffffu, pp, off);
            ss += __shfl_down_sync(0xffffffffu, ss, off);
        }
        if (lane == 0) {
            double pair = pp + (double)wd * (double)NN * (double)NN;
            float v = (float)((double)CONV * (ss + 0.5 * pair) * 0.01);
            if (isnan(v)) v = 1e-6f;
            out[w] = v;
        }
    }
    if (tid == 0) g_counter = 0;   // reset for next graph replay
}

extern "C" void kernel_launch(void* const* d_in, const int* in_sizes, int n_in,
                              void* d_out, int out_size) {
    const float* X    = (const float*)d_in[0];  // (B,N,3)
    const float* embs = (const float*)d_in[1];  // (B,N,C)
    const float* qs   = (const float*)d_in[2];  // (B,N)
    // d_in[3] = paired_mask (unused by reference)
    const float* born = (const float*)d_in[4];  // (C,)
    const float* die  = (const float*)d_in[5];  // (C,)
    const float* filt = (const float*)d_in[6];  // (2C+1, 1)
    float* out = (float*)d_out;

    precompute_kernel<<<PRE_BLOCKS, PRE_THREADS>>>(X, embs, qs, born, die, filt);
    pair_kernel<<<PBLOCKS, PTHREADS>>>(filt, out);
}

// round 13
// speedup vs baseline: 1.3088x; 1.0952x over previous
#include <cuda_runtime.h>
#include <math.h>

#define BB 4
#define NN 2048
#define CC 32
#define CONV 332.07156f
#define EPS 1e-6f

// ---- precompute geometry ----
#define PRE_THREADS 256
#define PRE_BLOCKS (BB * NN / PRE_THREADS)   // 32 (8 per batch)

// ---- pair geometry (symmetric 256-row panels, fine-grained) ----
#define PTHREADS 128
#define PIB 2                       // i-atoms per thread -> panel = 256
#define PANEL 256
#define BLKS_PER_B 370              // splits 82+72+62+51+41+31+21+10 (8 panels)
#define PBLOCKS (BB * BLKS_PER_B)   // 1480 = 10 CTAs/SM on 148 SMs

// Scratch (no cudaMalloc allowed)
__device__ float4 g_S[BB * NN];            // {-x, -y, -z, w=s_i+s_j}
__device__ double g_part_pair[PBLOCKS];
__device__ double g_part_self[PRE_BLOCKS]; // self + 0.5*diag-correction
__device__ unsigned int g_counter = 0;

// ============ kernel 1: per-atom precompute + self/diag partials ============
__global__ void __launch_bounds__(PRE_THREADS)
precompute_kernel(const float* __restrict__ X,
                  const float* __restrict__ embs,
                  const float* __restrict__ qs,
                  const float* __restrict__ born,
                  const float* __restrict__ die,
                  const float* __restrict__ filt)
{
    __shared__ double red[PRE_THREADS / 32];
    const int tid = threadIdx.x;
    const int idx = blockIdx.x * PRE_THREADS + tid;
    const float wd = filt[2 * CC];

    const float4* e4 = (const float4*)(embs + (long)idx * CC);
    const float4* fi = (const float4*)(filt);
    const float4* fj = (const float4*)(filt + CC);
    const float4* d4 = (const float4*)(die);
    const float4* b4 = (const float4*)(born);

    float si = 0.f, sj = 0.f, ad = EPS, R = 1.0f;
#pragma unroll
    for (int c = 0; c < CC / 4; c++) {
        float4 e = e4[c];
        float4 a = fi[c], bq = fj[c], d = d4[c], bo = b4[c];
        si = fmaf(e.x, a.x,  fmaf(e.y, a.y,  fmaf(e.z, a.z,  fmaf(e.w, a.w,  si))));
        sj = fmaf(e.x, bq.x, fmaf(e.y, bq.y, fmaf(e.z, bq.z, fmaf(e.w, bq.w, sj))));
        ad = fmaf(e.x, d.x,  fmaf(e.y, d.y,  fmaf(e.z, d.z,  fmaf(e.w, d.w,  ad))));
        R  = fmaf(e.x, bo.x, fmaf(e.y, bo.y, fmaf(e.z, bo.z, fmaf(e.w, bo.w, R))));
    }
    float es = -(1.0f - 1.0f / ad) * qs[idx] / (R + EPS);

    g_S[idx] = make_float4(-X[idx * 3 + 0], -X[idx * 3 + 1], -X[idx * 3 + 2],
                           si + sj);

    // exact diagonal correction: the pair loop credits (si+sj)*r0_hw + wd
    // for the j==i pair; the true value is (si+sj+wd*D0)/(D0+eps).
    double part;
    {
        float d2c = 3e-6f;
        asm volatile("" : "+f"(d2c));        // block constant folding
        float r0_hw = rsqrtf(d2c);           // identical MUFU value as pair loop
        double D0 = (double)sqrtf(d2c);
        double w  = (double)si + (double)sj;
        double exact = (w + (double)wd * D0) / (D0 + (double)EPS);
        double loopv = w * (double)r0_hw + (double)wd;
        double corr = exact - loopv;          // pair-sum channel (coeff 0.5)
        part = (double)es + 0.5 * corr;
    }
#pragma unroll
    for (int off = 16; off > 0; off >>= 1)
        part += __shfl_down_sync(0xffffffffu, part, off);
    if ((tid & 31) == 0) red[tid >> 5] = part;
    __syncthreads();
    if (tid == 0) {
        double s = 0.0;
#pragma unroll
        for (int w = 0; w < PRE_THREADS / 32; w++) s += red[w];
        g_part_self[blockIdx.x] = s;
    }
}

// ============ kernel 2: symmetric pairwise + finalize ============
// Full matrix T = sum_ij w_i r_ij decomposed per 256-row panel p:
//   intra-panel [lo, lo+256):        sum w_i r_ij (full sub-matrix)
//   cross-panel [lo+256, 2048) once: sum (w_i + w_j) r_ij
// E_pair(batch) = T + wd*N^2 (+exact diag corr from k1)
__global__ void __launch_bounds__(PTHREADS, 10)
pair_kernel(const float* __restrict__ filt, float* __restrict__ out)
{
    __shared__ float redf[PTHREADS / 32];
    __shared__ bool isLast;

    const int tid = threadIdx.x;
    const int blk = blockIdx.x;
    const int b   = blk / BLKS_PER_B;
    const int r   = blk % BLKS_PER_B;

    // panel + split within panel; splits: 82,72,62,51,41,31,21,10 (sum 370)
    int p, rl, ns;
    if      (r <  82) { p = 0; rl = r;       ns = 82; }
    else if (r < 154) { p = 1; rl = r -  82; ns = 72; }
    else if (r < 216) { p = 2; rl = r - 154; ns = 62; }
    else if (r < 267) { p = 3; rl = r - 216; ns = 51; }
    else if (r < 308) { p = 4; rl = r - 267; ns = 41; }
    else if (r < 339) { p = 5; rl = r - 308; ns = 31; }
    else if (r < 360) { p = 6; rl = r - 339; ns = 21; }
    else              { p = 7; rl = r - 360; ns = 10; }

    const int lo  = PANEL * p;
    const int len = NN - lo;
    const int j0  = lo + (rl * len) / ns;
    const int j1  = lo + ((rl + 1) * len) / ns;
    const int selfEnd = lo + PANEL;
    const int jA1 = (j1 < selfEnd) ? j1 : selfEnd;
    const int jB0 = (j0 > selfEnd) ? j0 : selfEnd;

    const float4* __restrict__ S = g_S + b * NN;

    // this thread's PIB i-atoms within the panel
    float xi[PIB], yi[PIB], zi[PIB], wi[PIB], acc[PIB];
#pragma unroll
    for (int k = 0; k < PIB; k++) {
        float4 a = __ldg(&S[lo + k * PTHREADS + tid]);
        xi[k] = -a.x; yi[k] = -a.y; zi[k] = -a.z; wi[k] = a.w;
        acc[k] = 0.f;
    }
    float accw = 0.f;

    // ---- loop A: intra-panel region (full matrix, w_i weight) ----
#pragma unroll 4
    for (int j = j0; j < jA1; j++) {
        float4 pj = __ldg(&S[j]);          // negated coords, warp-uniform
#pragma unroll
        for (int k = 0; k < PIB; k++) {
            float dx = xi[k] + pj.x;
            float dy = yi[k] + pj.y;
            float dz = zi[k] + pj.z;
            float d2 = fmaf(dx, dx, fmaf(dy, dy, fmaf(dz, dz, 3e-6f)));
            acc[k] += rsqrtf(d2);
        }
    }

    // ---- loop B: cross-panel region (counted once, (w_i + w_j) weight) ----
#pragma unroll 4
    for (int j = jB0; j < j1; j++) {
        float4 pj = __ldg(&S[j]);
#pragma unroll
        for (int k = 0; k < PIB; k++) {
            float dx = xi[k] + pj.x;
            float dy = yi[k] + pj.y;
            float dz = zi[k] + pj.z;
            float d2 = fmaf(dx, dx, fmaf(dy, dy, fmaf(dz, dz, 3e-6f)));
            float rr = rsqrtf(d2);
            acc[k] += rr;
            accw = fmaf(pj.w, rr, accw);   // w_j side of symmetric pair
        }
    }

    // ---- fp32 combine + warp reduce (FP64 only once per block, below) ----
    float part = accw;
#pragma unroll
    for (int k = 0; k < PIB; k++)
        part = fmaf(wi[k], acc[k], part);
#pragma unroll
    for (int off = 16; off > 0; off >>= 1)
        part += __shfl_down_sync(0xffffffffu, part, off);
    if ((tid & 31) == 0) redf[tid >> 5] = part;
    __syncthreads();
    if (tid == 0) {
        double s = 0.0;
#pragma unroll
        for (int w = 0; w < PTHREADS / 32; w++) s += (double)redf[w];
        g_part_pair[blk] = s;
        __threadfence();
        unsigned int t = atomicAdd(&g_counter, 1u);
        isLast = (t == (unsigned)(gridDim.x - 1));
    }
    __syncthreads();
    if (!isLast) return;

    // ---- finalize: warp w (w<BB) handles batch w ----
    const int w = tid >> 5, lane = tid & 31;
    const float wd = filt[2 * CC];

    if (w < BB) {
        double pp = 0.0;
#pragma unroll
        for (int t = 0; t < 12; t++) {
            int idx = lane + t * 32;
            if (idx < BLKS_PER_B) pp += __ldcg(&g_part_pair[w * BLKS_PER_B + idx]);
        }
        double ss = (lane < PRE_BLOCKS / BB)
                  ? __ldcg(&g_part_self[w * (PRE_BLOCKS / BB) + lane]) : 0.0;
#pragma unroll
        for (int off = 16; off > 0; off >>= 1) {
            pp += __shfl_down_sync(0xffffffffu, pp, off);
            ss += __shfl_down_sync(0xffffffffu, ss, off);
        }
        if (lane == 0) {
            double pair = pp + (double)wd * (double)NN * (double)NN;
            float v = (float)((double)CONV * (ss + 0.5 * pair) * 0.01);
            if (isnan(v)) v = 1e-6f;
            out[w] = v;
        }
    }
    if (tid == 0) g_counter = 0;   // reset for next graph replay
}

extern "C" void kernel_launch(void* const* d_in, const int* in_sizes, int n_in,
                              void* d_out, int out_size) {
    const float* X    = (const float*)d_in[0];  // (B,N,3)
    const float* embs = (const float*)d_in[1];  // (B,N,C)
    const float* qs   = (const float*)d_in[2];  // (B,N)
    // d_in[3] = paired_mask (unused by reference)
    const float* born = (const float*)d_in[4];  // (C,)
    const float* die  = (const float*)d_in[5];  // (C,)
    const float* filt = (const float*)d_in[6];  // (2C+1, 1)
    float* out = (float*)d_out;

    precompute_kernel<<<PRE_BLOCKS, PRE_THREADS>>>(X, embs, qs, born, die, filt);
    pair_kernel<<<PBLOCKS, PTHREADS>>>(filt, out);
}